// round 14
// baseline (speedup 1.0000x reference)
#include <cuda_runtime.h>
#include <cuda_fp16.h>
#include <cstdint>

// QueryConditionedRouter via mma.sync (HMMA) fp16 2-term split, 3 passes.
// R14: occupancy through SMALLER WARP TILES, not smaller blocks.
//      Warp tile 16 rows x 32 experts (acc 16 regs, core live set ~58):
//      256-thread blocks (B-cooperative) of 8 warps = 64 rows x 64 experts,
//      __launch_bounds__(256,4) -> 64-reg cap, 4 blocks/SM, 32 warps/SM.
//      Mainloop math per accumulator identical to R6/R13 -> same rel_err.
//   vis_emb  : (128, 576, 1024) f32  -> M = 73728 rows, K = 1024
//   query_emb: (8, 1024) f32
//   W_gate   : (64, 2048) f32
// Output (concat f32): topk_scores (M,2) | topk_idx (M,2) | gate_scores (M,64) | gate_logits (M,64)

#define MROWS   73728
#define KDIM    1024
#define NEXP    64
#define NBLOCKS (MROWS / 64)        // 1152 blocks, 64 rows each
#define ASCALE  4096.0f             // 2^12
#define BSCALE  32.0f               // 2^5
#define OSCALE  7.62939453125e-06f  // 2^-17

__device__ float g_qlog[512];
// B fragments, fragment-major: entry = ((chunk*8 + ntile)*32 + lane)
//   uint4 = { hi(k0,k1), hi(k2,k3), lo(k0,k1), lo(k2,k3) } with k = chunk*16 + 4*tig
__device__ uint4 g_bfrag[64 * 8 * 32];

__device__ __forceinline__ void split_pair(float f0, float f1, uint32_t &h, uint32_t &l) {
    __half2 hh = __floats2half2_rn(f0, f1);
    float g0 = __low2float(hh), g1 = __high2float(hh);
    __half2 ll = __floats2half2_rn(f0 - g0, f1 - g1);
    h = *reinterpret_cast<uint32_t*>(&hh);
    l = *reinterpret_cast<uint32_t*>(&ll);
}

// non-volatile, no memory clobber -> scheduler may reorder/interleave
__device__ __forceinline__ void mma16816(float* c, uint32_t a0, uint32_t a1, uint32_t a2,
                                         uint32_t a3, uint32_t b0, uint32_t b1) {
    asm("mma.sync.aligned.m16n8k16.row.col.f32.f16.f16.f32 "
        "{%0,%1,%2,%3}, {%4,%5,%6,%7}, {%8,%9}, {%0,%1,%2,%3};"
        : "+f"(c[0]), "+f"(c[1]), "+f"(c[2]), "+f"(c[3])
        : "r"(a0), "r"(a1), "r"(a2), "r"(a3), "r"(b0), "r"(b1));
}

__device__ __forceinline__ void prefetchL1(const void* p) {
    asm volatile("prefetch.global.L1 [%0];" :: "l"(p));
}

// ---------------------------------------------------------------------------
// Prep: (a) qry logits (one warp per (b,e)); (b) k-permuted B fragment build.
// ---------------------------------------------------------------------------
__global__ void qcr_prep_kernel(const float* __restrict__ qry, const float* __restrict__ Wg) {
    const int tid = blockIdx.x * 256 + threadIdx.x;
    {
        int w = tid >> 5, lane = tid & 31;
        const float* qp = qry + (size_t)(w >> 6) * KDIM;
        const float* wp = Wg + (size_t)(w & 63) * 2048 + 1024;
        float acc = 0.f;
        #pragma unroll 8
        for (int i = lane; i < KDIM; i += 32) acc += qp[i] * wp[i];
        #pragma unroll
        for (int o = 16; o; o >>= 1) acc += __shfl_xor_sync(0xffffffffu, acc, o);
        if (lane == 0) g_qlog[w] = acc;
    }
    {
        int lane = tid & 31;
        int t = (tid >> 5) & 7;           // n8 tile
        int c = tid >> 8;                 // k16 chunk
        int n = t * 8 + (lane >> 2);
        int k0 = c * 16 + (lane & 3) * 4; // permuted: contiguous 4 k per lane
        const float* wr = Wg + (size_t)n * 2048 + k0;
        uint4 v;
        split_pair(wr[0] * BSCALE, wr[1] * BSCALE, v.x, v.z);
        split_pair(wr[2] * BSCALE, wr[3] * BSCALE, v.y, v.w);
        g_bfrag[tid] = v;
    }
}

// ---------------------------------------------------------------------------
// Main: 1152 blocks x 256 threads (8 warps, 4 blocks/SM). Warp (rg = w>>1,
// eg = w&1): rows [rowbase + 16*rg, +16), experts [32*eg, +32).
// ---------------------------------------------------------------------------
__global__ void __launch_bounds__(256, 4) qcr_main_kernel(
    const float* __restrict__ vis,
    float* __restrict__ out)
{
    __shared__ float Ls[64 * 65];
    __shared__ float qrow[64];

    const int tid = threadIdx.x;
    const int warp = tid >> 5;
    const int lane = tid & 31;
    const int grp = lane >> 2;        // 0..7
    const int tig = lane & 3;         // 0..3
    const int rg = warp >> 1;         // 0..3 row group
    const int eg = warp & 1;          // 0..1 expert group
    const int rowbase = blockIdx.x * 64;

    if (tid < 64) qrow[tid] = g_qlog[(rowbase / 9216) * 64 + tid];

    const int r0 = rowbase + rg * 16 + grp;
    const float4* A0 = reinterpret_cast<const float4*>(vis + (size_t)r0 * KDIM) + tig;
    const float4* A1 = reinterpret_cast<const float4*>(vis + (size_t)(r0 + 8) * KDIM) + tig;
    const uint4* Bf = g_bfrag + lane;

    // per-warp A prefetch pointer: lane 0..15 -> the warp's 16 rows
    const float* Apf = vis + (size_t)(rowbase + rg * 16 + (lane & 15)) * KDIM;

    float acc[4][4];
    #pragma unroll
    for (int t = 0; t < 4; t++)
        #pragma unroll
        for (int j = 0; j < 4; j++) acc[t][j] = 0.f;

    if (lane < 16) {
        prefetchL1(Apf);
        prefetchL1(Apf + 32);
    }

    #pragma unroll 2
    for (int c = 0; c < 64; c++) {
        if ((c & 1) == 0 && c + 2 < 64 && lane < 16)
            prefetchL1(Apf + (c + 2) * 16);

        // ---- front-batch loads: A (2 x float4) then B (4 x uint4) ----
        float4 q0 = A0[c * 4];
        float4 q1 = A1[c * 4];
        uint4 b[4];
        #pragma unroll
        for (int t = 0; t < 4; t++) b[t] = Bf[(c * 8 + eg * 4 + t) * 32];

        uint32_t ah[4], al[4];
        split_pair(q0.x * ASCALE, q0.y * ASCALE, ah[0], al[0]);
        split_pair(q1.x * ASCALE, q1.y * ASCALE, ah[1], al[1]);
        split_pair(q0.z * ASCALE, q0.w * ASCALE, ah[2], al[2]);
        split_pair(q1.z * ASCALE, q1.w * ASCALE, ah[3], al[3]);

        // pass-major over the 4 tiles (RAW distance 4)
        #pragma unroll
        for (int t = 0; t < 4; t++)   // pass 0: Ahi * Bhi
            mma16816(acc[t], ah[0], ah[1], ah[2], ah[3], b[t].x, b[t].y);
        #pragma unroll
        for (int t = 0; t < 4; t++)   // pass 1: Ahi * Blo
            mma16816(acc[t], ah[0], ah[1], ah[2], ah[3], b[t].z, b[t].w);
        #pragma unroll
        for (int t = 0; t < 4; t++)   // pass 2: Alo * Bhi
            mma16816(acc[t], al[0], al[1], al[2], al[3], b[t].x, b[t].y);
    }

    // ---- stage logits to smem (rescale + add query logits) ----
    {
        const int rl0 = rg * 16 + grp;
        #pragma unroll
        for (int t = 0; t < 4; t++) {
            int col = eg * 32 + t * 8 + tig * 2;
            float q0 = qrow[col], q1 = qrow[col + 1];
            Ls[rl0 * 65 + col]           = acc[t][0] * OSCALE + q0;
            Ls[rl0 * 65 + col + 1]       = acc[t][1] * OSCALE + q1;
            Ls[(rl0 + 8) * 65 + col]     = acc[t][2] * OSCALE + q0;
            Ls[(rl0 + 8) * 65 + col + 1] = acc[t][3] * OSCALE + q1;
        }
    }
    __syncthreads();

    // ---- per-row softmax + top-2 + outputs; smem-resident ----
    const size_t O_TI = 2 * (size_t)MROWS;
    const size_t O_SC = 4 * (size_t)MROWS;
    const size_t O_LG = O_SC + (size_t)MROWS * NEXP;

    if (tid < 64) {
        const float* Lr = Ls + tid * 65;   // stride 65: conflict-free

        float m1 = -1e30f, m2 = -1e30f;
        int i1 = 0, i2 = 0;
        #pragma unroll
        for (int e = 0; e < 64; e++) {
            float v = Lr[e];
            if (v > m1) { m2 = m1; i2 = i1; m1 = v; i1 = e; }
            else if (v > m2) { m2 = v; i2 = e; }
        }

        float ssum = 0.f;
        #pragma unroll
        for (int e = 0; e < 64; e++) ssum += __expf(Lr[e] - m1);
        float inv = 1.0f / ssum;

        size_t g = (size_t)(rowbase + tid);
        out[g * 2 + 0] = inv;
        out[g * 2 + 1] = __expf(m2 - m1) * inv;
        out[O_TI + g * 2 + 0] = (float)i1;
        out[O_TI + g * 2 + 1] = (float)i2;

        float4* sc = reinterpret_cast<float4*>(out + O_SC + g * 64);
        float4* lg = reinterpret_cast<float4*>(out + O_LG + g * 64);
        #pragma unroll
        for (int e4 = 0; e4 < 16; e4++) {
            float4 lv = make_float4(Lr[e4 * 4], Lr[e4 * 4 + 1], Lr[e4 * 4 + 2], Lr[e4 * 4 + 3]);
            lg[e4] = lv;
            sc[e4] = make_float4(__expf(lv.x - m1) * inv, __expf(lv.y - m1) * inv,
                                 __expf(lv.z - m1) * inv, __expf(lv.w - m1) * inv);
        }
    }
}

// ---------------------------------------------------------------------------
extern "C" void kernel_launch(void* const* d_in, const int* in_sizes, int n_in,
                              void* d_out, int out_size)
{
    const float* vis = (const float*)d_in[0];
    const float* qry = (const float*)d_in[1];
    const float* Wg  = (const float*)d_in[2];
    float* out = (float*)d_out;

    qcr_prep_kernel<<<64, 256>>>(qry, Wg);
    qcr_main_kernel<<<NBLOCKS, 256>>>(vis, out);
}

// round 15
// speedup vs baseline: 1.2970x; 1.2970x over previous
#include <cuda_runtime.h>
#include <cuda_fp16.h>
#include <cstdint>

// QueryConditionedRouter via mma.sync (HMMA) fp16 2-term split, 3 passes.
// R15 = R12 (k-permuted B, pass-major MMA, prefetch, smem epilogue)
//       + WARP PHASE STAGGER: warps 4-7 start the k-loop at chunk 32
//       (wrap-around). Each SMSP holds one warp of each phase group, so
//       load windows of one group overlap MMA issue of the other --
//       breaks the block-wide phase lock that serialized L1 and tensor.
//   vis_emb  : (128, 576, 1024) f32  -> M = 73728 rows, K = 1024
//   query_emb: (8, 1024) f32
//   W_gate   : (64, 2048) f32
// Output (concat f32): topk_scores (M,2) | topk_idx (M,2) | gate_scores (M,64) | gate_logits (M,64)

#define MROWS   73728
#define KDIM    1024
#define NEXP    64
#define NBLOCKS (MROWS / 128)       // 576
#define ASCALE  4096.0f             // 2^12
#define BSCALE  32.0f               // 2^5
#define OSCALE  7.62939453125e-06f  // 2^-17

__device__ float g_qlog[512];
// B fragments, fragment-major: entry = ((chunk*8 + ntile)*32 + lane)
//   uint4 = { hi(k0,k1), hi(k2,k3), lo(k0,k1), lo(k2,k3) } with k = chunk*16 + 4*tig
//   (k-permuted so the A side uses one contiguous float4 per row-group per chunk)
__device__ uint4 g_bfrag[64 * 8 * 32];

__device__ __forceinline__ void split_pair(float f0, float f1, uint32_t &h, uint32_t &l) {
    __half2 hh = __floats2half2_rn(f0, f1);
    float g0 = __low2float(hh), g1 = __high2float(hh);
    __half2 ll = __floats2half2_rn(f0 - g0, f1 - g1);
    h = *reinterpret_cast<uint32_t*>(&hh);
    l = *reinterpret_cast<uint32_t*>(&ll);
}

// non-volatile, no memory clobber -> scheduler may reorder/interleave
__device__ __forceinline__ void mma16816(float* c, uint32_t a0, uint32_t a1, uint32_t a2,
                                         uint32_t a3, uint32_t b0, uint32_t b1) {
    asm("mma.sync.aligned.m16n8k16.row.col.f32.f16.f16.f32 "
        "{%0,%1,%2,%3}, {%4,%5,%6,%7}, {%8,%9}, {%0,%1,%2,%3};"
        : "+f"(c[0]), "+f"(c[1]), "+f"(c[2]), "+f"(c[3])
        : "r"(a0), "r"(a1), "r"(a2), "r"(a3), "r"(b0), "r"(b1));
}

__device__ __forceinline__ void prefetchL1(const void* p) {
    asm volatile("prefetch.global.L1 [%0];" :: "l"(p));
}

// ---------------------------------------------------------------------------
// Prep: (a) qry logits (one warp per (b,e)); (b) k-permuted B fragment build.
// ---------------------------------------------------------------------------
__global__ void qcr_prep_kernel(const float* __restrict__ qry, const float* __restrict__ Wg) {
    const int tid = blockIdx.x * 256 + threadIdx.x;
    {
        int w = tid >> 5, lane = tid & 31;
        const float* qp = qry + (size_t)(w >> 6) * KDIM;
        const float* wp = Wg + (size_t)(w & 63) * 2048 + 1024;
        float acc = 0.f;
        #pragma unroll 8
        for (int i = lane; i < KDIM; i += 32) acc += qp[i] * wp[i];
        #pragma unroll
        for (int o = 16; o; o >>= 1) acc += __shfl_xor_sync(0xffffffffu, acc, o);
        if (lane == 0) g_qlog[w] = acc;
    }
    {
        int lane = tid & 31;
        int t = (tid >> 5) & 7;           // n8 tile
        int c = tid >> 8;                 // k16 chunk
        int n = t * 8 + (lane >> 2);
        int k0 = c * 16 + (lane & 3) * 4; // permuted: contiguous 4 k per lane
        const float* wr = Wg + (size_t)n * 2048 + k0;
        uint4 v;
        split_pair(wr[0] * BSCALE, wr[1] * BSCALE, v.x, v.z);
        split_pair(wr[2] * BSCALE, wr[3] * BSCALE, v.y, v.w);
        g_bfrag[tid] = v;
    }
}

// ---------------------------------------------------------------------------
// Main: 576 blocks x 256 threads (8 warps, 2 blocks/SM). Warp w: rows
// [rowbase+16w, +16), all 64 experts. Warps 4-7 phase-shifted by 32 chunks.
// ---------------------------------------------------------------------------
__global__ void __launch_bounds__(256, 2) qcr_main_kernel(
    const float* __restrict__ vis,
    float* __restrict__ out)
{
    __shared__ float Ls[128 * 65];
    __shared__ float qrow[64];

    const int tid = threadIdx.x;
    const int warp = tid >> 5;
    const int lane = tid & 31;
    const int grp = lane >> 2;        // 0..7
    const int tig = lane & 3;         // 0..3
    const int rowbase = blockIdx.x * 128;

    if (tid < 64) qrow[tid] = g_qlog[(rowbase / 9216) * 64 + tid];

    const int r0 = rowbase + warp * 16 + grp;
    const float4* A0 = reinterpret_cast<const float4*>(vis + (size_t)r0 * KDIM) + tig;
    const float4* A1 = reinterpret_cast<const float4*>(vis + (size_t)(r0 + 8) * KDIM) + tig;
    const uint4* Bf = g_bfrag + lane;

    // per-warp A prefetch pointer: lane 0..15 -> the warp's 16 rows
    const float* Apf = vis + (size_t)(rowbase + warp * 16 + (lane & 15)) * KDIM;

    // phase stagger: warps 0-3 start at chunk 0, warps 4-7 at chunk 32.
    // SMSP s holds wids {s, s+4} -> one warp of each phase per scheduler.
    const int cbase = (warp & 4) << 3;     // 0 or 32

    float acc[8][4];
    #pragma unroll
    for (int t = 0; t < 8; t++)
        #pragma unroll
        for (int j = 0; j < 4; j++) acc[t][j] = 0.f;

    // warm this phase group's first two chunk-pairs' A lines
    if (lane < 16) {
        prefetchL1(Apf + cbase * 16);
        prefetchL1(Apf + cbase * 16 + 32);
    }

    #pragma unroll 2
    for (int cc = 0; cc < 64; cc++) {
        const int c = (cc + cbase) & 63;   // wrap-around chunk index

        // register-free A prefetch, 2 chunks ahead (even iters, lanes 0..15)
        if ((cc & 1) == 0 && cc + 2 < 64 && lane < 16)
            prefetchL1(Apf + (((cc + 2 + cbase) & 63)) * 16);

        // A fragment: rows (r0, r0+8), actual k = c*16 + 4tig .. +3 (permuted)
        float4 q0 = A0[c * 4];
        float4 q1 = A1[c * 4];

        uint32_t ah[4], al[4];
        split_pair(q0.x * ASCALE, q0.y * ASCALE, ah[0], al[0]);
        split_pair(q1.x * ASCALE, q1.y * ASCALE, ah[1], al[1]);
        split_pair(q0.z * ASCALE, q0.w * ASCALE, ah[2], al[2]);
        split_pair(q1.z * ASCALE, q1.w * ASCALE, ah[3], al[3]);

        // tiles in groups of 4, pass-major inside the group (RAW distance 4)
        #pragma unroll
        for (int g = 0; g < 2; g++) {
            uint4 b[4];
            #pragma unroll
            for (int t = 0; t < 4; t++) b[t] = Bf[(c * 8 + g * 4 + t) * 32];

            #pragma unroll
            for (int t = 0; t < 4; t++)   // pass 0: Ahi * Bhi
                mma16816(acc[g * 4 + t], ah[0], ah[1], ah[2], ah[3], b[t].x, b[t].y);
            #pragma unroll
            for (int t = 0; t < 4; t++)   // pass 1: Ahi * Blo
                mma16816(acc[g * 4 + t], ah[0], ah[1], ah[2], ah[3], b[t].z, b[t].w);
            #pragma unroll
            for (int t = 0; t < 4; t++)   // pass 2: Alo * Bhi
                mma16816(acc[g * 4 + t], al[0], al[1], al[2], al[3], b[t].x, b[t].y);
        }
    }

    // ---- stage logits to smem (rescale + add query logits) ----
    {
        const int rl0 = warp * 16 + grp;
        #pragma unroll
        for (int t = 0; t < 8; t++) {
            int col = t * 8 + tig * 2;
            float q0 = qrow[col], q1 = qrow[col + 1];
            Ls[rl0 * 65 + col]           = acc[t][0] * OSCALE + q0;
            Ls[rl0 * 65 + col + 1]       = acc[t][1] * OSCALE + q1;
            Ls[(rl0 + 8) * 65 + col]     = acc[t][2] * OSCALE + q0;
            Ls[(rl0 + 8) * 65 + col + 1] = acc[t][3] * OSCALE + q1;
        }
    }
    __syncthreads();

    // ---- per-row softmax + top-2 + outputs; smem-resident ----
    const size_t O_TI = 2 * (size_t)MROWS;
    const size_t O_SC = 4 * (size_t)MROWS;
    const size_t O_LG = O_SC + (size_t)MROWS * NEXP;

    if (tid < 128) {
        const float* Lr = Ls + tid * 65;   // stride 65: conflict-free

        float m1 = -1e30f, m2 = -1e30f;
        int i1 = 0, i2 = 0;
        #pragma unroll
        for (int e = 0; e < 64; e++) {
            float v = Lr[e];
            if (v > m1) { m2 = m1; i2 = i1; m1 = v; i1 = e; }
            else if (v > m2) { m2 = v; i2 = e; }
        }

        float ssum = 0.f;
        #pragma unroll
        for (int e = 0; e < 64; e++) ssum += __expf(Lr[e] - m1);
        float inv = 1.0f / ssum;

        size_t g = (size_t)(rowbase + tid);
        out[g * 2 + 0] = inv;
        out[g * 2 + 1] = __expf(m2 - m1) * inv;
        out[O_TI + g * 2 + 0] = (float)i1;
        out[O_TI + g * 2 + 1] = (float)i2;

        float4* sc = reinterpret_cast<float4*>(out + O_SC + g * 64);
        float4* lg = reinterpret_cast<float4*>(out + O_LG + g * 64);
        #pragma unroll
        for (int e4 = 0; e4 < 16; e4++) {
            float4 lv = make_float4(Lr[e4 * 4], Lr[e4 * 4 + 1], Lr[e4 * 4 + 2], Lr[e4 * 4 + 3]);
            lg[e4] = lv;
            sc[e4] = make_float4(__expf(lv.x - m1) * inv, __expf(lv.y - m1) * inv,
                                 __expf(lv.z - m1) * inv, __expf(lv.w - m1) * inv);
        }
    }
}

// ---------------------------------------------------------------------------
extern "C" void kernel_launch(void* const* d_in, const int* in_sizes, int n_in,
                              void* d_out, int out_size)
{
    const float* vis = (const float*)d_in[0];
    const float* qry = (const float*)d_in[1];
    const float* Wg  = (const float*)d_in[2];
    float* out = (float*)d_out;

    qcr_prep_kernel<<<64, 256>>>(qry, Wg);
    qcr_main_kernel<<<NBLOCKS, 256>>>(vis, out);
}